// round 15
// baseline (speedup 1.0000x reference)
#include <cuda_runtime.h>
#include <cuda_fp16.h>
#include <cstdint>

#define BATCH 8
#define LEN   512
#define DIM   768
#define MAXW  12
#define NSPAN (LEN * MAXW)          // 6144
#define MROWS (BATCH * LEN)         // 4096

// ---------------------------------------------------------------------------
// Scratch (static device arrays; no allocation allowed)
// ---------------------------------------------------------------------------
__device__ __half g_h[MROWS * DIM];          // fp16(h)
__device__ __half g_S[MROWS * DIM];          // fp16(relu(h@Ws+bs))
__device__ __half g_E[MROWS * DIM];          // fp16(relu(h@We+be))
// Weights [K][N] fp16: [0]=Ws, [1]=We, [2]=Wo_top, [3]=Wo_bot
__device__ __half g_W[4 * DIM * DIM];
__device__ __half g_P[MROWS * DIM];          // fp16(S @ Wo_top)
__device__ __half g_Q[MROWS * DIM];          // fp16(E @ Wo_bot)

// ---------------------------------------------------------------------------
// Fused fp32 -> fp16 convert: blockIdx.y = 0:h, 1:Ws, 2:We, 3:Wo
// ---------------------------------------------------------------------------
__global__ void conv_all_kernel(const float* __restrict__ h,
                                const float* __restrict__ Ws,
                                const float* __restrict__ We,
                                const float* __restrict__ Wo)
{
    const int region = blockIdx.y;
    const int W4 = (DIM * DIM) / 4;   // 147456
    const float* src;
    __half* dst;
    int n4;
    switch (region) {
        case 0: src = h;  dst = g_h;                  n4 = (MROWS * DIM) / 4; break; // 786432
        case 1: src = Ws; dst = g_W;                  n4 = W4; break;
        case 2: src = We; dst = g_W + DIM * DIM;      n4 = W4; break;
        default: src = Wo; dst = g_W + 2 * DIM * DIM; n4 = 2 * W4; break;
    }
    int i = blockIdx.x * blockDim.x + threadIdx.x;
    if (i >= n4) return;
    float4 v = ((const float4*)src)[i];
    ((__half2*)dst)[i * 2 + 0] = __floats2half2_rn(v.x, v.y);
    ((__half2*)dst)[i * 2 + 1] = __floats2half2_rn(v.z, v.w);
}

// ---------------------------------------------------------------------------
// MMA / async-copy helpers (fp16)
// ---------------------------------------------------------------------------
__device__ __forceinline__ void ldsm_x4(uint32_t* r, uint32_t addr)
{
    asm volatile("ldmatrix.sync.aligned.m8n8.x4.shared.b16 {%0,%1,%2,%3}, [%4];"
                 : "=r"(r[0]), "=r"(r[1]), "=r"(r[2]), "=r"(r[3]) : "r"(addr));
}
__device__ __forceinline__ void ldsm_x4_t(uint32_t* r, uint32_t addr)
{
    asm volatile("ldmatrix.sync.aligned.m8n8.x4.trans.shared.b16 {%0,%1,%2,%3}, [%4];"
                 : "=r"(r[0]), "=r"(r[1]), "=r"(r[2]), "=r"(r[3]) : "r"(addr));
}
__device__ __forceinline__ void mma_f16(float* c, const uint32_t* a, const uint32_t* b)
{
    asm volatile("mma.sync.aligned.m16n8k16.row.col.f32.f16.f16.f32 "
                 "{%0,%1,%2,%3}, {%4,%5,%6,%7}, {%8,%9}, {%0,%1,%2,%3};"
                 : "+f"(c[0]), "+f"(c[1]), "+f"(c[2]), "+f"(c[3])
                 : "r"(a[0]), "r"(a[1]), "r"(a[2]), "r"(a[3]), "r"(b[0]), "r"(b[1]));
}
__device__ __forceinline__ void cp16(uint32_t saddr, const void* gaddr)
{
    asm volatile("cp.async.cg.shared.global [%0], [%1], 16;" :: "r"(saddr), "l"(gaddr));
}
__device__ __forceinline__ void cp_commit() { asm volatile("cp.async.commit_group;"); }
template <int N> __device__ __forceinline__ void cp_wait()
{
    asm volatile("cp.async.wait_group %0;" :: "n"(N));
}

// ---------------------------------------------------------------------------
// Single-term fp16 tensor-core GEMM, 3-stage cp.async pipeline, BK=64.
// BM=128, BN=128, BK=64. 128 threads = 4 warps (2m x 2n), warp tile 64x64.
// 2 CTAs/SM. One __syncthreads per iter; 12 iters (half the barriers of BK=32).
// Grid per launch: (6, 32) = 192 CTAs; S->P and E->Q chains on two streams.
// ---------------------------------------------------------------------------
#define ASTR 72                      // A smem row stride (elems), conflict-free
#define BSTR 136                     // B smem row stride (elems)
#define A_BYTES (128 * ASTR * 2)     // 18432
#define B_BYTES (64 * BSTR * 2)      // 17408
#define STG_BYTES (A_BYTES + B_BYTES)       // 35840
#define NSTAGE 3
#define SMEM_TOTAL (NSTAGE * STG_BYTES)     // 107520
#define NIT (DIM / 64)               // 12

template <bool STAGE1>
__device__ __forceinline__ void gemm_body(
    const __half* __restrict__ A,
    const __half* __restrict__ W,
    const float* __restrict__ bias,
    __half* __restrict__ Oh)
{
    extern __shared__ char smem[];
    const uint32_t smem_base = (uint32_t)__cvta_generic_to_shared(smem);

    const int tid  = threadIdx.x;          // 0..127
    const int lane = tid & 31;
    const int w    = tid >> 5;             // 0..3
    const int wm   = (w >> 1) * 64;        // warp m offset (0 or 64)
    const int wn   = (w & 1) * 64;         // warp n offset (0 or 64)
    const int bm   = blockIdx.y * 128;
    const int bn   = blockIdx.x * 128;

    // A: 128x64 = 1024 16B-chunks, 8/thread: c = tid+i*128, row=c>>3, col=(c&7)*8
    // B: 64x128 = 1024 chunks, 8/thread: row = c>>4, col = (c&15)*8
    auto issue_stage = [&](int stg, int k0) {
        const uint32_t sa = smem_base + stg * STG_BYTES;
        const uint32_t sb = sa + A_BYTES;
#pragma unroll
        for (int i = 0; i < 8; i++) {
            int c = tid + i * 128;
            int ar = c >> 3, ac = (c & 7) * 8;
            cp16(sa + ar * (ASTR * 2) + ac * 2,
                 A + (size_t)(bm + ar) * DIM + k0 + ac);
        }
#pragma unroll
        for (int i = 0; i < 8; i++) {
            int c = tid + i * 128;
            int br = c >> 4, bc2 = (c & 15) * 8;
            cp16(sb + br * (BSTR * 2) + bc2 * 2,
                 W + (size_t)(k0 + br) * DIM + bn + bc2);
        }
        cp_commit();
    };

    float acc[4][8][4];
#pragma unroll
    for (int i = 0; i < 4; i++)
#pragma unroll
        for (int j = 0; j < 8; j++)
#pragma unroll
            for (int k = 0; k < 4; k++) acc[i][j][k] = 0.0f;

    issue_stage(0, 0);
    issue_stage(1, 64);

    for (int it = 0; it < NIT; it++) {
        cp_wait<1>();          // stage it%3 landed (1 newer may fly)
        __syncthreads();       // all warps done with iter it-1 -> slot (it+2)%3 free

        if (it + 2 < NIT) issue_stage((it + 2) % NSTAGE, (it + 2) * 64);

        const int stg = it % NSTAGE;
        const uint32_t sa = smem_base + stg * STG_BYTES;
        const uint32_t sb = sa + A_BYTES;

#pragma unroll
        for (int kk = 0; kk < 64; kk += 16) {
            uint32_t af[4][4], bf[8][2];
#pragma unroll
            for (int mi = 0; mi < 4; mi++) {
                uint32_t off = (wm + mi * 16 + (lane & 15)) * (ASTR * 2)
                             + (kk + (lane >> 4) * 8) * 2;
                ldsm_x4(af[mi], sa + off);
            }
#pragma unroll
            for (int ni = 0; ni < 4; ni++) {
                uint32_t off = (kk + (lane & 15)) * (BSTR * 2)
                             + (wn + ni * 16 + (lane >> 4) * 8) * 2;
                uint32_t rb[4];
                ldsm_x4_t(rb, sb + off);
                bf[ni * 2][0] = rb[0]; bf[ni * 2][1] = rb[1];
                bf[ni * 2 + 1][0] = rb[2]; bf[ni * 2 + 1][1] = rb[3];
            }
#pragma unroll
            for (int mi = 0; mi < 4; mi++)
#pragma unroll
                for (int nj = 0; nj < 8; nj++)
                    mma_f16(acc[mi][nj], af[mi], bf[nj]);
        }
    }

    // Epilogue. c-frag: c0,c1 -> (row=lane>>2, col=(lane&3)*2+{0,1}); c2,c3 -> row+8.
    const int er = lane >> 2;
    const int ec = (lane & 3) * 2;
#pragma unroll
    for (int mi = 0; mi < 4; mi++) {
#pragma unroll
        for (int nj = 0; nj < 8; nj++) {
            int m0 = bm + wm + mi * 16 + er;
            int n0 = bn + wn + nj * 8 + ec;
            float v0 = acc[mi][nj][0], v1 = acc[mi][nj][1];
            float v2 = acc[mi][nj][2], v3 = acc[mi][nj][3];
            if (STAGE1) {
                float b0 = bias[n0], b1 = bias[n0 + 1];
                v0 = fmaxf(v0 + b0, 0.0f); v1 = fmaxf(v1 + b1, 0.0f);
                v2 = fmaxf(v2 + b0, 0.0f); v3 = fmaxf(v3 + b1, 0.0f);
            }
            *(__half2*)&Oh[(size_t)m0 * DIM + n0]       = __floats2half2_rn(v0, v1);
            *(__half2*)&Oh[(size_t)(m0 + 8) * DIM + n0] = __floats2half2_rn(v2, v3);
        }
    }
}

// which: 0 = S-chain, 1 = E-chain
__global__ __launch_bounds__(128, 2)
void stage1_kernel(const float* __restrict__ bias, int which)
{
    if (which == 0)
        gemm_body<true>(g_h, g_W, bias, g_S);
    else
        gemm_body<true>(g_h, g_W + DIM * DIM, bias, g_E);
}

__global__ __launch_bounds__(128, 2)
void stage2_kernel(int which)
{
    if (which == 0)
        gemm_body<false>(g_S, g_W + 2 * DIM * DIM, nullptr, g_P);
    else
        gemm_body<false>(g_E, g_W + 3 * DIM * DIM, nullptr, g_Q);
}

// ---------------------------------------------------------------------------
// Gather-add: out[b,n,:] = fp32(P16[b,idx_s]) + fp32(Q16[b,idx_e]) + bo
// 8 rows per thread (16 independent gathered loads), streaming stores.
// ---------------------------------------------------------------------------
__global__ void gather_add_kernel(const int* __restrict__ span_idx,
                                  const float* __restrict__ bo,
                                  float* __restrict__ out)
{
    const int base = blockIdx.x * 32;
    const int ty = threadIdx.y;                 // 0..3
    const int t  = threadIdx.x;                 // 0..191 -> halves 4t..4t+3
    float4 bv = __ldg(&((const float4*)bo)[t]);

    int rows[8];
    const uint2* pp[8];
    const uint2* qq[8];
#pragma unroll
    for (int j = 0; j < 8; j++) {
        int r = base + j * 4 + ty;
        int b = r / NSPAN;
        int is = span_idx[r * 2], ie = span_idx[r * 2 + 1];
        rows[j] = r;
        pp[j] = (const uint2*)(g_P + (size_t)(b * LEN + is) * DIM);
        qq[j] = (const uint2*)(g_Q + (size_t)(b * LEN + ie) * DIM);
    }
    uint2 pv[8], qv[8];
#pragma unroll
    for (int j = 0; j < 8; j++) pv[j] = pp[j][t];
#pragma unroll
    for (int j = 0; j < 8; j++) qv[j] = qq[j][t];
#pragma unroll
    for (int j = 0; j < 8; j++) {
        float2 p01 = __half22float2(*(const __half2*)&pv[j].x);
        float2 p23 = __half22float2(*(const __half2*)&pv[j].y);
        float2 q01 = __half22float2(*(const __half2*)&qv[j].x);
        float2 q23 = __half22float2(*(const __half2*)&qv[j].y);
        float4 o = make_float4(p01.x + q01.x + bv.x,
                               p01.y + q01.y + bv.y,
                               p23.x + q23.x + bv.z,
                               p23.y + q23.y + bv.w);
        __stcs(&((float4*)(out + (size_t)rows[j] * DIM))[t], o);
    }
}

extern "C" void kernel_launch(void* const* d_in, const int* in_sizes, int n_in,
                              void* d_out, int out_size)
{
    (void)in_sizes; (void)n_in; (void)out_size;
    const float* h    = (const float*)d_in[0];
    const int*   span = (const int*)d_in[1];
    const float* Ws   = (const float*)d_in[2];
    const float* bs   = (const float*)d_in[3];
    const float* We   = (const float*)d_in[4];
    const float* be   = (const float*)d_in[5];
    const float* Wo   = (const float*)d_in[6];
    const float* bo   = (const float*)d_in[7];
    float* out = (float*)d_out;

    // One-time resources (created on the first, uncaptured correctness call)
    static cudaStream_t s_side = nullptr;
    static cudaEvent_t ev_fork = nullptr, ev_join = nullptr;
    if (!s_side) {
        cudaFuncSetAttribute(stage1_kernel,
                             cudaFuncAttributeMaxDynamicSharedMemorySize, SMEM_TOTAL);
        cudaFuncSetAttribute(stage2_kernel,
                             cudaFuncAttributeMaxDynamicSharedMemorySize, SMEM_TOTAL);
        cudaStreamCreateWithFlags(&s_side, cudaStreamNonBlocking);
        cudaEventCreateWithFlags(&ev_fork, cudaEventDisableTiming);
        cudaEventCreateWithFlags(&ev_join, cudaEventDisableTiming);
    }

    conv_all_kernel<<<dim3(3072, 4), 256>>>(h, Ws, We, Wo);

    dim3 ggrid(DIM / 128, MROWS / 128);                // (6, 32) = 192 CTAs

    // Fork: side stream runs the S->P chain, main stream runs E->Q.
    cudaEventRecord(ev_fork, 0);
    cudaStreamWaitEvent(s_side, ev_fork, 0);

    stage1_kernel<<<ggrid, 128, SMEM_TOTAL, s_side>>>(bs, 0);   // S
    stage2_kernel<<<ggrid, 128, SMEM_TOTAL, s_side>>>(0);       // P
    cudaEventRecord(ev_join, s_side);

    stage1_kernel<<<ggrid, 128, SMEM_TOTAL>>>(be, 1);           // E
    stage2_kernel<<<ggrid, 128, SMEM_TOTAL>>>(1);               // Q

    // Join: gather needs both P and Q.
    cudaStreamWaitEvent(0, ev_join, 0);
    dim3 gblock(192, 4);
    gather_add_kernel<<<(BATCH * NSPAN) / 32, gblock>>>(span, bo, out);
}

// round 16
// speedup vs baseline: 1.1734x; 1.1734x over previous
#include <cuda_runtime.h>
#include <cuda_fp16.h>
#include <cstdint>

#define BATCH 8
#define LEN   512
#define DIM   768
#define MAXW  12
#define NSPAN (LEN * MAXW)          // 6144
#define MROWS (BATCH * LEN)         // 4096

// ---------------------------------------------------------------------------
// Scratch (static device arrays; no allocation allowed)
// ---------------------------------------------------------------------------
__device__ __half g_h[MROWS * DIM];          // fp16(h)
__device__ __half g_S[MROWS * DIM];          // fp16(relu(h@Ws+bs))
__device__ __half g_E[MROWS * DIM];          // fp16(relu(h@We+be))
// Weights [K][N] fp16: [0]=Ws, [1]=We, [2]=Wo_top, [3]=Wo_bot
__device__ __half g_W[4 * DIM * DIM];
__device__ __half g_P[MROWS * DIM];          // fp16(S @ Wo_top)
__device__ __half g_Q[MROWS * DIM];          // fp16(E @ Wo_bot)

// ---------------------------------------------------------------------------
// Fused fp32 -> fp16 convert: blockIdx.y = 0:h, 1:Ws, 2:We, 3:Wo
// ---------------------------------------------------------------------------
__global__ void conv_all_kernel(const float* __restrict__ h,
                                const float* __restrict__ Ws,
                                const float* __restrict__ We,
                                const float* __restrict__ Wo)
{
    const int region = blockIdx.y;
    const int W4 = (DIM * DIM) / 4;   // 147456
    const float* src;
    __half* dst;
    int n4;
    switch (region) {
        case 0: src = h;  dst = g_h;                  n4 = (MROWS * DIM) / 4; break; // 786432
        case 1: src = Ws; dst = g_W;                  n4 = W4; break;
        case 2: src = We; dst = g_W + DIM * DIM;      n4 = W4; break;
        default: src = Wo; dst = g_W + 2 * DIM * DIM; n4 = 2 * W4; break;
    }
    int i = blockIdx.x * blockDim.x + threadIdx.x;
    if (i >= n4) return;
    float4 v = ((const float4*)src)[i];
    ((__half2*)dst)[i * 2 + 0] = __floats2half2_rn(v.x, v.y);
    ((__half2*)dst)[i * 2 + 1] = __floats2half2_rn(v.z, v.w);
}

// ---------------------------------------------------------------------------
// MMA / async-copy helpers (fp16)
// ---------------------------------------------------------------------------
__device__ __forceinline__ void ldsm_x4(uint32_t* r, uint32_t addr)
{
    asm volatile("ldmatrix.sync.aligned.m8n8.x4.shared.b16 {%0,%1,%2,%3}, [%4];"
                 : "=r"(r[0]), "=r"(r[1]), "=r"(r[2]), "=r"(r[3]) : "r"(addr));
}
__device__ __forceinline__ void ldsm_x4_t(uint32_t* r, uint32_t addr)
{
    asm volatile("ldmatrix.sync.aligned.m8n8.x4.trans.shared.b16 {%0,%1,%2,%3}, [%4];"
                 : "=r"(r[0]), "=r"(r[1]), "=r"(r[2]), "=r"(r[3]) : "r"(addr));
}
__device__ __forceinline__ void mma_f16(float* c, const uint32_t* a, const uint32_t* b)
{
    asm volatile("mma.sync.aligned.m16n8k16.row.col.f32.f16.f16.f32 "
                 "{%0,%1,%2,%3}, {%4,%5,%6,%7}, {%8,%9}, {%0,%1,%2,%3};"
                 : "+f"(c[0]), "+f"(c[1]), "+f"(c[2]), "+f"(c[3])
                 : "r"(a[0]), "r"(a[1]), "r"(a[2]), "r"(a[3]), "r"(b[0]), "r"(b[1]));
}
__device__ __forceinline__ void cp16(uint32_t saddr, const void* gaddr)
{
    asm volatile("cp.async.cg.shared.global [%0], [%1], 16;" :: "r"(saddr), "l"(gaddr));
}
__device__ __forceinline__ void cp_commit() { asm volatile("cp.async.commit_group;"); }
template <int N> __device__ __forceinline__ void cp_wait()
{
    asm volatile("cp.async.wait_group %0;" :: "n"(N));
}

// ---------------------------------------------------------------------------
// Single-term fp16 tensor-core GEMM, 4-stage cp.async pipeline.
// R14 config (measured best): BM=128, BN=128, BK=32, 128 threads = 4 warps
// (2m x 2n), warp tile 64x64, 2 CTAs/SM, one __syncthreads per iter.
// Grid per launch: (6, 32) = 192 CTAs; S->P and E->Q chains on two streams.
// ---------------------------------------------------------------------------
#define ASTR 40                      // A smem row stride (elems)
#define BSTR 136                     // B smem row stride (elems)
#define A_BYTES (128 * ASTR * 2)     // 10240
#define B_BYTES (32 * BSTR * 2)      // 8704
#define STG_BYTES (A_BYTES + B_BYTES)       // 18944
#define NSTAGE 4
#define SMEM_TOTAL (NSTAGE * STG_BYTES)     // 75776
#define NIT (DIM / 32)               // 24

template <bool STAGE1>
__device__ __forceinline__ void gemm_body(
    const __half* __restrict__ A,
    const __half* __restrict__ W,
    const float* __restrict__ bias,
    __half* __restrict__ Oh)
{
    extern __shared__ char smem[];
    const uint32_t smem_base = (uint32_t)__cvta_generic_to_shared(smem);

    const int tid  = threadIdx.x;          // 0..127
    const int lane = tid & 31;
    const int w    = tid >> 5;             // 0..3
    const int wm   = (w >> 1) * 64;        // warp m offset (0 or 64)
    const int wn   = (w & 1) * 64;         // warp n offset (0 or 64)
    const int bm   = blockIdx.y * 128;
    const int bn   = blockIdx.x * 128;

    auto issue_stage = [&](int stg, int k0) {
        const uint32_t sa = smem_base + stg * STG_BYTES;
        const uint32_t sb = sa + A_BYTES;
#pragma unroll
        for (int i = 0; i < 4; i++) {
            int c = tid + i * 128;
            int ar = c >> 2, ac = (c & 3) * 8;
            cp16(sa + ar * (ASTR * 2) + ac * 2,
                 A + (size_t)(bm + ar) * DIM + k0 + ac);
        }
#pragma unroll
        for (int i = 0; i < 4; i++) {
            int c = tid + i * 128;
            int br = c >> 4, bc2 = (c & 15) * 8;
            cp16(sb + br * (BSTR * 2) + bc2 * 2,
                 W + (size_t)(k0 + br) * DIM + bn + bc2);
        }
        cp_commit();
    };

    float acc[4][8][4];
#pragma unroll
    for (int i = 0; i < 4; i++)
#pragma unroll
        for (int j = 0; j < 8; j++)
#pragma unroll
            for (int k = 0; k < 4; k++) acc[i][j][k] = 0.0f;

    issue_stage(0, 0);
    issue_stage(1, 32);
    issue_stage(2, 64);

    for (int it = 0; it < NIT; it++) {
        cp_wait<2>();          // stage it%4 has landed (2 newer may fly)
        __syncthreads();       // all warps done with iter it-1 -> slot (it+3)%4 free

        if (it + 3 < NIT) issue_stage((it + 3) % NSTAGE, (it + 3) * 32);

        const int stg = it % NSTAGE;
        const uint32_t sa = smem_base + stg * STG_BYTES;
        const uint32_t sb = sa + A_BYTES;

#pragma unroll
        for (int kk = 0; kk < 32; kk += 16) {
            uint32_t af[4][4], bf[8][2];
#pragma unroll
            for (int mi = 0; mi < 4; mi++) {
                uint32_t off = (wm + mi * 16 + (lane & 15)) * (ASTR * 2)
                             + (kk + (lane >> 4) * 8) * 2;
                ldsm_x4(af[mi], sa + off);
            }
#pragma unroll
            for (int ni = 0; ni < 4; ni++) {
                uint32_t off = (kk + (lane & 15)) * (BSTR * 2)
                             + (wn + ni * 16 + (lane >> 4) * 8) * 2;
                uint32_t rb[4];
                ldsm_x4_t(rb, sb + off);
                bf[ni * 2][0] = rb[0]; bf[ni * 2][1] = rb[1];
                bf[ni * 2 + 1][0] = rb[2]; bf[ni * 2 + 1][1] = rb[3];
            }
#pragma unroll
            for (int mi = 0; mi < 4; mi++)
#pragma unroll
                for (int nj = 0; nj < 8; nj++)
                    mma_f16(acc[mi][nj], af[mi], bf[nj]);
        }
    }

    // Epilogue. c-frag: c0,c1 -> (row=lane>>2, col=(lane&3)*2+{0,1}); c2,c3 -> row+8.
    const int er = lane >> 2;
    const int ec = (lane & 3) * 2;
#pragma unroll
    for (int mi = 0; mi < 4; mi++) {
#pragma unroll
        for (int nj = 0; nj < 8; nj++) {
            int m0 = bm + wm + mi * 16 + er;
            int n0 = bn + wn + nj * 8 + ec;
            float v0 = acc[mi][nj][0], v1 = acc[mi][nj][1];
            float v2 = acc[mi][nj][2], v3 = acc[mi][nj][3];
            if (STAGE1) {
                float b0 = bias[n0], b1 = bias[n0 + 1];
                v0 = fmaxf(v0 + b0, 0.0f); v1 = fmaxf(v1 + b1, 0.0f);
                v2 = fmaxf(v2 + b0, 0.0f); v3 = fmaxf(v3 + b1, 0.0f);
            }
            *(__half2*)&Oh[(size_t)m0 * DIM + n0]       = __floats2half2_rn(v0, v1);
            *(__half2*)&Oh[(size_t)(m0 + 8) * DIM + n0] = __floats2half2_rn(v2, v3);
        }
    }
}

// which: 0 = S-chain, 1 = E-chain
__global__ __launch_bounds__(128, 2)
void stage1_kernel(const float* __restrict__ bias, int which)
{
    if (which == 0)
        gemm_body<true>(g_h, g_W, bias, g_S);
    else
        gemm_body<true>(g_h, g_W + DIM * DIM, bias, g_E);
}

__global__ __launch_bounds__(128, 2)
void stage2_kernel(int which)
{
    if (which == 0)
        gemm_body<false>(g_S, g_W + 2 * DIM * DIM, nullptr, g_P);
    else
        gemm_body<false>(g_E, g_W + 3 * DIM * DIM, nullptr, g_Q);
}

// ---------------------------------------------------------------------------
// Gather-add: out[b,n,:] = fp32(P16[b,idx_s]) + fp32(Q16[b,idx_e]) + bo
// 4 rows per thread (8 independent gathered loads). Block (192,2) = 384
// threads -> 5 blocks/SM (93.75% theoretical occupancy vs 75% at 768).
// ---------------------------------------------------------------------------
__global__ __launch_bounds__(384)
void gather_add_kernel(const int* __restrict__ span_idx,
                       const float* __restrict__ bo,
                       float* __restrict__ out)
{
    const int base = blockIdx.x * 8;
    const int ty = threadIdx.y;                 // 0..1
    const int t  = threadIdx.x;                 // 0..191 -> halves 4t..4t+3
    float4 bv = __ldg(&((const float4*)bo)[t]);

    int rows[4];
    const uint2* pp[4];
    const uint2* qq[4];
#pragma unroll
    for (int j = 0; j < 4; j++) {
        int r = base + j * 2 + ty;
        int b = r / NSPAN;
        int is = span_idx[r * 2], ie = span_idx[r * 2 + 1];
        rows[j] = r;
        pp[j] = (const uint2*)(g_P + (size_t)(b * LEN + is) * DIM);
        qq[j] = (const uint2*)(g_Q + (size_t)(b * LEN + ie) * DIM);
    }
    uint2 pv[4], qv[4];
#pragma unroll
    for (int j = 0; j < 4; j++) pv[j] = pp[j][t];
#pragma unroll
    for (int j = 0; j < 4; j++) qv[j] = qq[j][t];
#pragma unroll
    for (int j = 0; j < 4; j++) {
        float2 p01 = __half22float2(*(const __half2*)&pv[j].x);
        float2 p23 = __half22float2(*(const __half2*)&pv[j].y);
        float2 q01 = __half22float2(*(const __half2*)&qv[j].x);
        float2 q23 = __half22float2(*(const __half2*)&qv[j].y);
        float4 o = make_float4(p01.x + q01.x + bv.x,
                               p01.y + q01.y + bv.y,
                               p23.x + q23.x + bv.z,
                               p23.y + q23.y + bv.w);
        __stcs(&((float4*)(out + (size_t)rows[j] * DIM))[t], o);
    }
}

extern "C" void kernel_launch(void* const* d_in, const int* in_sizes, int n_in,
                              void* d_out, int out_size)
{
    (void)in_sizes; (void)n_in; (void)out_size;
    const float* h    = (const float*)d_in[0];
    const int*   span = (const int*)d_in[1];
    const float* Ws   = (const float*)d_in[2];
    const float* bs   = (const float*)d_in[3];
    const float* We   = (const float*)d_in[4];
    const float* be   = (const float*)d_in[5];
    const float* Wo   = (const float*)d_in[6];
    const float* bo   = (const float*)d_in[7];
    float* out = (float*)d_out;

    // One-time resources (created on the first, uncaptured correctness call)
    static cudaStream_t s_side = nullptr;
    static cudaEvent_t ev_fork = nullptr, ev_join = nullptr;
    if (!s_side) {
        cudaFuncSetAttribute(stage1_kernel,
                             cudaFuncAttributeMaxDynamicSharedMemorySize, SMEM_TOTAL);
        cudaFuncSetAttribute(stage2_kernel,
                             cudaFuncAttributeMaxDynamicSharedMemorySize, SMEM_TOTAL);
        cudaStreamCreateWithFlags(&s_side, cudaStreamNonBlocking);
        cudaEventCreateWithFlags(&ev_fork, cudaEventDisableTiming);
        cudaEventCreateWithFlags(&ev_join, cudaEventDisableTiming);
    }

    conv_all_kernel<<<dim3(3072, 4), 256>>>(h, Ws, We, Wo);

    dim3 ggrid(DIM / 128, MROWS / 128);                // (6, 32) = 192 CTAs

    // Fork: side stream runs the S->P chain, main stream runs E->Q.
    cudaEventRecord(ev_fork, 0);
    cudaStreamWaitEvent(s_side, ev_fork, 0);

    stage1_kernel<<<ggrid, 128, SMEM_TOTAL, s_side>>>(bs, 0);   // S
    stage2_kernel<<<ggrid, 128, SMEM_TOTAL, s_side>>>(0);       // P
    cudaEventRecord(ev_join, s_side);

    stage1_kernel<<<ggrid, 128, SMEM_TOTAL>>>(be, 1);           // E
    stage2_kernel<<<ggrid, 128, SMEM_TOTAL>>>(1);               // Q

    // Join: gather needs both P and Q.
    cudaStreamWaitEvent(0, ev_join, 0);
    dim3 gblock(192, 2);
    gather_add_kernel<<<(BATCH * NSPAN) / 8, gblock>>>(span, bo, out);
}